// round 1
// baseline (speedup 1.0000x reference)
#include <cuda_runtime.h>

typedef unsigned long long ull;

#define BATCH 4
#define NHEAD 16
#define SEQ   1024
#define DIM   64
#define NBH   (BATCH * NHEAD)   // 64
#define LOG2E 1.4426950408889634f

// scratch: rel_h / rel_w logit tables, pre-scaled by log2(e)
// layout: [bh][s][k] with k in 0..31
__device__ __align__(16) float g_relH[NBH * SEQ * 32];
__device__ __align__(16) float g_relW[NBH * SEQ * 32];

// ---------- f32x2 helpers ----------
__device__ __forceinline__ ull pack2(float x, float y) {
    ull r; asm("mov.b64 %0, {%1,%2};" : "=l"(r) : "f"(x), "f"(y)); return r;
}
__device__ __forceinline__ void unpack2(ull p, float& x, float& y) {
    asm("mov.b64 {%0,%1}, %2;" : "=f"(x), "=f"(y) : "l"(p));
}
__device__ __forceinline__ void fma2(ull& d, ull a, ull b) {
    asm("fma.rn.f32x2 %0, %1, %2, %0;" : "+l"(d) : "l"(a), "l"(b));
}
__device__ __forceinline__ ull mul2(ull a, ull b) {
    ull r; asm("mul.rn.f32x2 %0, %1, %2;" : "=l"(r) : "l"(a), "l"(b)); return r;
}
__device__ __forceinline__ float ex2f(float x) {
    float r; asm("ex2.approx.f32 %0, %1;" : "=f"(r) : "f"(x)); return r;
}

// ---------- kernel A: rel_h / rel_w precompute ----------
// one warp per q-row; lane = relative-position index k (0..31)
__global__ void rel_kernel(const float* __restrict__ q,
                           const float* __restrict__ rph,
                           const float* __restrict__ rpw)
{
    __shared__ float4 sQ[4][16];
    const int wid  = threadIdx.x >> 5;
    const int lane = threadIdx.x & 31;
    const int r    = blockIdx.x * 4 + wid;     // row id in [0, 64*1024)
    const int bh = r >> 10, s = r & 1023;
    const int b = bh >> 4, hd = bh & 15;
    const int h = s >> 5,  w = s & 31;

    const float* qrow = q + (((size_t)(b * SEQ + s) * NHEAD + hd) << 6);
    // load 64 floats of this q row into smem (2 per lane, as float4 by 8 lanes... simple path)
    ((float*)sQ[wid])[lane]      = qrow[lane];
    ((float*)sQ[wid])[lane + 32] = qrow[lane + 32];
    __syncwarp();

    const float4* Rh = (const float4*)(rph + (size_t)(h - lane + 31) * DIM);
    const float4* Rw = (const float4*)(rpw + (size_t)(w - lane + 31) * DIM);

    float ah = 0.f, aw = 0.f;
    #pragma unroll
    for (int f = 0; f < 16; f++) {
        float4 qv = sQ[wid][f];
        float4 hv = Rh[f];
        float4 wv = Rw[f];
        ah += qv.x * hv.x + qv.y * hv.y + qv.z * hv.z + qv.w * hv.w;
        aw += qv.x * wv.x + qv.y * wv.y + qv.z * wv.z + qv.w * wv.w;
    }
    g_relH[(size_t)r * 32 + lane] = ah * LOG2E;
    g_relW[(size_t)r * 32 + lane] = aw * LOG2E;
}

// ---------- kernel B: fp32 flash attention with f32x2 FMAs ----------
// grid: (16 m-tiles, 64 heads), block: 128 threads (tx 0..15, ty 0..7)
// thread tile: 8 rows (m = ty*8..+7, paired for f32x2) x 4 cols (n/d = tx*4..+3)
__global__ void __launch_bounds__(128, 3)
flash_kernel(const float* __restrict__ q, const float* __restrict__ k,
             const float* __restrict__ v, float* __restrict__ out)
{
    extern __shared__ float smbuf[];
    float* Qt  = smbuf;                 // [64][72]  transposed Q * (0.125*log2e)
    float* KP  = smbuf + 64 * 72;       // [64][65]  K tile, later reused as P tile
    float* Vs  = KP + 64 * 65;          // [64][64]  V tile, natural layout
    float* rHs = Vs + 64 * 64;          // [64][32]
    float* rWs = rHs + 64 * 32;         // [64][32]

    const int tid = threadIdx.x;
    const int tx  = tid & 15;
    const int ty  = tid >> 4;
    const int m0  = blockIdx.x << 6;
    const int bh  = blockIdx.y;
    const int b   = bh >> 4, hd = bh & 15;
    const int rs  = NHEAD * DIM;        // 1024 floats between consecutive s

    const size_t hoff = (size_t)b * SEQ * rs + (size_t)hd * DIM;
    const float* qh = q + hoff;
    const float* kh = k + hoff;
    const float* vh = v + hoff;
    float*       oh = out + hoff;

    // ---- load Q tile transposed (scaled), and rel tables ----
    {
        const float qscale = 0.125f * LOG2E;
        const int r  = tid >> 1;
        const int c0 = (tid & 1) << 5;
        const float4* src = (const float4*)(qh + (size_t)(m0 + r) * rs + c0);
        #pragma unroll
        for (int f = 0; f < 8; f++) {
            float4 x = src[f];
            int c = c0 + f * 4;
            Qt[(c + 0) * 72 + r] = x.x * qscale;
            Qt[(c + 1) * 72 + r] = x.y * qscale;
            Qt[(c + 2) * 72 + r] = x.z * qscale;
            Qt[(c + 3) * 72 + r] = x.w * qscale;
        }
        const float4* rh4 = (const float4*)(g_relH + ((size_t)bh * SEQ + m0) * 32);
        const float4* rw4 = (const float4*)(g_relW + ((size_t)bh * SEQ + m0) * 32);
        #pragma unroll
        for (int f = 0; f < 4; f++) {
            ((float4*)rHs)[tid + f * 128] = rh4[tid + f * 128];
            ((float4*)rWs)[tid + f * 128] = rw4[tid + f * 128];
        }
    }

    ull   Oa[8][2];                 // O accumulator: rows r, d-pairs
    float rowm[8], rowl[8];
    #pragma unroll
    for (int r = 0; r < 8; r++) {
        Oa[r][0] = 0ull; Oa[r][1] = 0ull;
        rowm[r] = -3.0e38f; rowl[r] = 0.f;
    }

    const int mrow = ty << 3;

    for (int n0 = 0; n0 < SEQ; n0 += 64) {
        __syncthreads();  // prev PV reads of KP/Vs done; also covers Q/rel loads on iter 0
        // ---- load K (stride-65) and V (natural) tiles ----
        {
            const int r  = tid >> 1;
            const int c0 = (tid & 1) << 5;
            const float4* ksrc = (const float4*)(kh + (size_t)(n0 + r) * rs + c0);
            const float4* vsrc = (const float4*)(vh + (size_t)(n0 + r) * rs + c0);
            float*  kd = KP + r * 65 + c0;
            float4* vd = (float4*)(Vs + r * 64 + c0);
            #pragma unroll
            for (int f = 0; f < 8; f++) {
                float4 kx = ksrc[f];
                kd[f * 4 + 0] = kx.x; kd[f * 4 + 1] = kx.y;
                kd[f * 4 + 2] = kx.z; kd[f * 4 + 3] = kx.w;
                vd[f] = vsrc[f];
            }
        }
        __syncthreads();

        // ---- S = (Q*scale*log2e) K^T  : f32x2 accumulators paired over m ----
        ull Sa[4][4];
        #pragma unroll
        for (int i = 0; i < 4; i++)
            #pragma unroll
            for (int j = 0; j < 4; j++) Sa[i][j] = 0ull;

        #pragma unroll 8
        for (int c = 0; c < DIM; c++) {
            const ull* qp = (const ull*)(Qt + c * 72 + mrow);
            ull a0 = qp[0], a1 = qp[1], a2v = qp[2], a3 = qp[3];
            #pragma unroll
            for (int j = 0; j < 4; j++) {
                float bv = KP[(tx * 4 + j) * 65 + c];
                ull b2 = pack2(bv, bv);
                fma2(Sa[0][j], a0, b2);
                fma2(Sa[1][j], a1, b2);
                fma2(Sa[2][j], a2v, b2);
                fma2(Sa[3][j], a3, b2);
            }
        }

        // ---- unpack, add rel logits (already *log2e), online softmax ----
        float sv[8][4];
        #pragma unroll
        for (int i = 0; i < 4; i++)
            #pragma unroll
            for (int j = 0; j < 4; j++)
                unpack2(Sa[i][j], sv[2 * i][j], sv[2 * i + 1][j]);

        const int khid = (n0 >> 5) + (tx >> 3);   // all 4 cols of this thread share kh
        #pragma unroll
        for (int r = 0; r < 8; r++) {
            float rh = rHs[(mrow + r) * 32 + khid];
            #pragma unroll
            for (int j = 0; j < 4; j++)
                sv[r][j] += rh + rWs[(mrow + r) * 32 + ((tx * 4 + j) & 31)];
        }

        #pragma unroll
        for (int r = 0; r < 8; r++) {
            float mx = fmaxf(fmaxf(sv[r][0], sv[r][1]), fmaxf(sv[r][2], sv[r][3]));
            mx = fmaxf(mx, __shfl_xor_sync(0xffffffffu, mx, 1));
            mx = fmaxf(mx, __shfl_xor_sync(0xffffffffu, mx, 2));
            mx = fmaxf(mx, __shfl_xor_sync(0xffffffffu, mx, 4));
            mx = fmaxf(mx, __shfl_xor_sync(0xffffffffu, mx, 8));
            float mnew  = fmaxf(rowm[r], mx);
            float alpha = ex2f(rowm[r] - mnew);
            rowm[r] = mnew;
            ull al2 = pack2(alpha, alpha);
            Oa[r][0] = mul2(Oa[r][0], al2);
            Oa[r][1] = mul2(Oa[r][1], al2);
            float ps = 0.f;
            #pragma unroll
            for (int j = 0; j < 4; j++) {
                float pv = ex2f(sv[r][j] - mnew);
                sv[r][j] = pv;
                ps += pv;
            }
            rowl[r] = rowl[r] * alpha + ps;
        }

        __syncthreads();  // all warps done reading KP as K
        // ---- store P into KP as [m][n], stride 65 ----
        #pragma unroll
        for (int r = 0; r < 8; r++)
            #pragma unroll
            for (int j = 0; j < 4; j++)
                KP[(mrow + r) * 65 + tx * 4 + j] = sv[r][j];
        __syncthreads();

        // ---- O += P V  : f32x2 accumulators paired over d ----
        #pragma unroll 8
        for (int n = 0; n < 64; n++) {
            const ull* vp = (const ull*)(Vs + n * 64 + tx * 4);
            ull b0 = vp[0], b1 = vp[1];
            #pragma unroll
            for (int r = 0; r < 8; r++) {
                float av = KP[(mrow + r) * 65 + n];
                ull a2p = pack2(av, av);
                fma2(Oa[r][0], a2p, b0);
                fma2(Oa[r][1], a2p, b1);
            }
        }
    }

    // ---- finalize: reduce row sums over tx, normalize, store ----
    #pragma unroll
    for (int r = 0; r < 8; r++) {
        float l = rowl[r];
        l += __shfl_xor_sync(0xffffffffu, l, 1);
        l += __shfl_xor_sync(0xffffffffu, l, 2);
        l += __shfl_xor_sync(0xffffffffu, l, 4);
        l += __shfl_xor_sync(0xffffffffu, l, 8);
        float inv = __fdividef(1.0f, l);
        float x0, x1, x2, x3;
        unpack2(Oa[r][0], x0, x1);
        unpack2(Oa[r][1], x2, x3);
        float4 o = make_float4(x0 * inv, x1 * inv, x2 * inv, x3 * inv);
        *(float4*)(oh + (size_t)(m0 + mrow + r) * rs + tx * 4) = o;
    }
}

extern "C" void kernel_launch(void* const* d_in, const int* in_sizes, int n_in,
                              void* d_out, int out_size)
{
    const float* q   = (const float*)d_in[0];
    const float* k   = (const float*)d_in[1];
    const float* v   = (const float*)d_in[2];
    const float* rph = (const float*)d_in[3];
    const float* rpw = (const float*)d_in[4];
    float* out = (float*)d_out;

    // kernel A: rel logit tables (64*1024 rows, 4 rows per block)
    rel_kernel<<<(NBH * SEQ) / 4, 128>>>(q, rph, rpw);

    // kernel B: flash attention
    const int smem = (64 * 72 + 64 * 65 + 64 * 64 + 64 * 32 + 64 * 32) * 4;  // 67840 B
    cudaFuncSetAttribute(flash_kernel, cudaFuncAttributeMaxDynamicSharedMemorySize, smem);
    dim3 grid(SEQ / 64, NBH);
    flash_kernel<<<grid, 128, smem>>>(q, k, v, out);
}